// round 2
// baseline (speedup 1.0000x reference)
#include <cuda_runtime.h>
#include <math.h>

// Problem constants
#define HDIM 1024
#define IDIM 4096
#define NEXP 8
#define TOPK 2
#define NTOK 4096          // B*S
#define NSLOT 8192         // NTOK * TOPK

// GEMM tiling
#define TM 128
#define TN 64
#define KC 16
#define PAD_MAX 9216       // NSLOT + NEXP*TM padding headroom
#define TILE_MAX 72        // NSLOT/TM + NEXP

// Scratch (static __device__ — no allocation at launch time)
__device__ int   g_perm[PAD_MAX];
__device__ int   g_tile_expert[TILE_MAX];
__device__ int   g_tile_row0[TILE_MAX];
__device__ float g_act[(size_t)PAD_MAX * IDIM];   // silu(g)*u, padded-row major
__device__ float g_y[(size_t)NSLOT * HDIM];       // per-slot down output (weighted)

// ---------------------------------------------------------------------------
// Routing: counting-sort 8192 slots into per-expert segments padded to TM rows.
// Single block. Output permutation order is non-deterministic (smem atomics)
// but the final kernel output is invariant to it: every FP reduction order is
// fixed per slot, and g_y is scattered by original slot id.
// ---------------------------------------------------------------------------
__global__ void route_kernel(const int* __restrict__ ei) {
    __shared__ int cnt[NEXP];
    __shared__ int cur[NEXP];
    int tid = threadIdx.x;
    if (tid < NEXP) cnt[tid] = 0;
    __syncthreads();
    for (int s = tid; s < NSLOT; s += blockDim.x)
        atomicAdd(&cnt[ei[s]], 1);
    __syncthreads();
    if (tid == 0) {
        int base = 0, tile = 0;
        for (int e = 0; e < NEXP; e++) {
            cur[e] = base;
            int nt = (cnt[e] + TM - 1) / TM;
            for (int j = 0; j < nt; j++) {
                g_tile_expert[tile] = e;
                g_tile_row0[tile]   = base + j * TM;
                tile++;
            }
            base += nt * TM;
        }
        for (; tile < TILE_MAX; tile++) g_tile_expert[tile] = -1;
    }
    __syncthreads();
    for (int r = tid; r < PAD_MAX; r += blockDim.x) g_perm[r] = -1;
    __syncthreads();
    for (int s = tid; s < NSLOT; s += blockDim.x) {
        int e = ei[s];
        int pos = atomicAdd(&cur[e], 1);
        g_perm[pos] = s;
    }
}

__device__ __forceinline__ float silu_mul(float g, float u) {
    // silu(g) * u = g * sigmoid(g) * u
    return g * u / (1.0f + expf(-g));
}

// ---------------------------------------------------------------------------
// GEMM1: act[r, i] = silu(x[tok(r)] . gate[e][i]) * (x[tok(r)] . up[e][i])
// Tile: TM=128 rows x TN=64 I-cols, K-chunk 16. 256 threads, 8x4 per thread,
// two accumulator sets (gate & up) sharing the x tile.
// ---------------------------------------------------------------------------
__global__ __launch_bounds__(256)
void gemm1_kernel(const float* __restrict__ x,
                  const float* __restrict__ gate,
                  const float* __restrict__ up) {
    int e = g_tile_expert[blockIdx.y];
    if (e < 0) return;
    int row0 = g_tile_row0[blockIdx.y];
    int i0 = blockIdx.x * TN;

    __shared__ float xs[KC][TM];
    __shared__ float wg[KC][TN];
    __shared__ float wu[KC][TN];
    __shared__ int   toks[TM];

    int tid = threadIdx.y * 16 + threadIdx.x;
    if (tid < TM) {
        int p = g_perm[row0 + tid];
        toks[tid] = (p >= 0) ? (p >> 1) : -1;   // token = slot / TOPK
    }
    __syncthreads();

    float accg[8][4];
    float accu[8][4];
#pragma unroll
    for (int r = 0; r < 8; r++)
#pragma unroll
        for (int c = 0; c < 4; c++) { accg[r][c] = 0.f; accu[r][c] = 0.f; }

    int mload = tid & (TM - 1);        // 0..127
    int kq2   = tid >> 7;              // 0..1
    int nload = tid & (TN - 1);        // 0..63
    int kqw   = tid >> 6;              // 0..3

    int tok = toks[mload];
    const float* xptr = (tok >= 0) ? (x + (size_t)tok * HDIM) : (const float*)0;
    const float* gptr = gate + ((size_t)e * IDIM + (i0 + nload)) * HDIM + kqw * 4;
    const float* uptr = up   + ((size_t)e * IDIM + (i0 + nload)) * HDIM + kqw * 4;

    for (int h0 = 0; h0 < HDIM; h0 += KC) {
        // stage x tile (transposed)
#pragma unroll
        for (int q = 0; q < 2; q++) {
            int kc = (kq2 * 2 + q) * 4;
            float4 v = make_float4(0.f, 0.f, 0.f, 0.f);
            if (xptr) v = *(const float4*)(xptr + h0 + kc);
            xs[kc + 0][mload] = v.x; xs[kc + 1][mload] = v.y;
            xs[kc + 2][mload] = v.z; xs[kc + 3][mload] = v.w;
        }
        // stage weight tiles (transposed)
        {
            int kc = kqw * 4;
            float4 v = *(const float4*)(gptr + h0);
            wg[kc + 0][nload] = v.x; wg[kc + 1][nload] = v.y;
            wg[kc + 2][nload] = v.z; wg[kc + 3][nload] = v.w;
            float4 w = *(const float4*)(uptr + h0);
            wu[kc + 0][nload] = w.x; wu[kc + 1][nload] = w.y;
            wu[kc + 2][nload] = w.z; wu[kc + 3][nload] = w.w;
        }
        __syncthreads();
#pragma unroll
        for (int k = 0; k < KC; k++) {
            float a[8];
            float4 a0 = *(const float4*)&xs[k][threadIdx.y * 8];
            float4 a1 = *(const float4*)&xs[k][threadIdx.y * 8 + 4];
            a[0] = a0.x; a[1] = a0.y; a[2] = a0.z; a[3] = a0.w;
            a[4] = a1.x; a[5] = a1.y; a[6] = a1.z; a[7] = a1.w;
            float4 bg = *(const float4*)&wg[k][threadIdx.x * 4];
            float4 bu = *(const float4*)&wu[k][threadIdx.x * 4];
#pragma unroll
            for (int r = 0; r < 8; r++) {
                accg[r][0] += a[r] * bg.x; accg[r][1] += a[r] * bg.y;
                accg[r][2] += a[r] * bg.z; accg[r][3] += a[r] * bg.w;
                accu[r][0] += a[r] * bu.x; accu[r][1] += a[r] * bu.y;
                accu[r][2] += a[r] * bu.z; accu[r][3] += a[r] * bu.w;
            }
        }
        __syncthreads();
    }

#pragma unroll
    for (int r = 0; r < 8; r++) {
        int row = threadIdx.y * 8 + r;
        float4 o;
        o.x = silu_mul(accg[r][0], accu[r][0]);
        o.y = silu_mul(accg[r][1], accu[r][1]);
        o.z = silu_mul(accg[r][2], accu[r][2]);
        o.w = silu_mul(accg[r][3], accu[r][3]);
        *(float4*)&g_act[(size_t)(row0 + row) * IDIM + i0 + threadIdx.x * 4] = o;
    }
}

// ---------------------------------------------------------------------------
// GEMM2: y[slot, h] = ew[slot] * (act[r, :] . down[e][h, :]), K = IDIM
// ---------------------------------------------------------------------------
__global__ __launch_bounds__(256)
void gemm2_kernel(const float* __restrict__ down,
                  const float* __restrict__ ew) {
    int e = g_tile_expert[blockIdx.y];
    if (e < 0) return;
    int row0 = g_tile_row0[blockIdx.y];
    int h0 = blockIdx.x * TN;

    __shared__ float as_[KC][TM];
    __shared__ float ws[KC][TN];
    __shared__ int   slots[TM];
    __shared__ float swt[TM];

    int tid = threadIdx.y * 16 + threadIdx.x;
    if (tid < TM) {
        int p = g_perm[row0 + tid];
        slots[tid] = p;
        swt[tid] = (p >= 0) ? ew[p] : 0.f;
    }
    __syncthreads();

    float acc[8][4];
#pragma unroll
    for (int r = 0; r < 8; r++)
#pragma unroll
        for (int c = 0; c < 4; c++) acc[r][c] = 0.f;

    int mload = tid & (TM - 1);
    int kq2   = tid >> 7;
    int nload = tid & (TN - 1);
    int kqw   = tid >> 6;

    const float* aptr = &g_act[(size_t)(row0 + mload) * IDIM];
    const float* wptr = down + ((size_t)e * HDIM + (h0 + nload)) * IDIM + kqw * 4;

    for (int i0 = 0; i0 < IDIM; i0 += KC) {
#pragma unroll
        for (int q = 0; q < 2; q++) {
            int kc = (kq2 * 2 + q) * 4;
            float4 v = *(const float4*)(aptr + i0 + kc);
            as_[kc + 0][mload] = v.x; as_[kc + 1][mload] = v.y;
            as_[kc + 2][mload] = v.z; as_[kc + 3][mload] = v.w;
        }
        {
            int kc = kqw * 4;
            float4 v = *(const float4*)(wptr + i0);
            ws[kc + 0][nload] = v.x; ws[kc + 1][nload] = v.y;
            ws[kc + 2][nload] = v.z; ws[kc + 3][nload] = v.w;
        }
        __syncthreads();
#pragma unroll
        for (int k = 0; k < KC; k++) {
            float a[8];
            float4 a0 = *(const float4*)&as_[k][threadIdx.y * 8];
            float4 a1 = *(const float4*)&as_[k][threadIdx.y * 8 + 4];
            a[0] = a0.x; a[1] = a0.y; a[2] = a0.z; a[3] = a0.w;
            a[4] = a1.x; a[5] = a1.y; a[6] = a1.z; a[7] = a1.w;
            float4 b = *(const float4*)&ws[k][threadIdx.x * 4];
#pragma unroll
            for (int r = 0; r < 8; r++) {
                acc[r][0] += a[r] * b.x; acc[r][1] += a[r] * b.y;
                acc[r][2] += a[r] * b.z; acc[r][3] += a[r] * b.w;
            }
        }
        __syncthreads();
    }

#pragma unroll
    for (int r = 0; r < 8; r++) {
        int row = threadIdx.y * 8 + r;
        int p = slots[row];
        if (p >= 0) {
            float w = swt[row];
            float4 o;
            o.x = acc[r][0] * w; o.y = acc[r][1] * w;
            o.z = acc[r][2] * w; o.w = acc[r][3] * w;
            *(float4*)&g_y[(size_t)p * HDIM + h0 + threadIdx.x * 4] = o;
        }
    }
}

// ---------------------------------------------------------------------------
// Combine: out[t, h] = y[2t, h] + y[2t+1, h]
// ---------------------------------------------------------------------------
__global__ void combine_kernel(float* __restrict__ out) {
    const int HQ = HDIM / 4;
    int i = blockIdx.x * blockDim.x + threadIdx.x;
    if (i >= NTOK * HQ) return;
    int t = i / HQ, hq = i - t * HQ;
    const float4* y4 = (const float4*)g_y;
    float4 a = y4[(size_t)(2 * t) * HQ + hq];
    float4 b = y4[(size_t)(2 * t + 1) * HQ + hq];
    float4 o;
    o.x = a.x + b.x; o.y = a.y + b.y; o.z = a.z + b.z; o.w = a.w + b.w;
    ((float4*)out)[(size_t)t * HQ + hq] = o;
}

extern "C" void kernel_launch(void* const* d_in, const int* in_sizes, int n_in,
                              void* d_out, int out_size) {
    const float* x    = (const float*)d_in[0];
    const int*   ei   = (const int*)d_in[1];
    const float* ew   = (const float*)d_in[2];
    const float* gate = (const float*)d_in[3];
    const float* up   = (const float*)d_in[4];
    const float* down = (const float*)d_in[5];
    float* out = (float*)d_out;

    route_kernel<<<1, 256>>>(ei);

    dim3 blk(16, 16);
    gemm1_kernel<<<dim3(IDIM / TN, TILE_MAX), blk>>>(x, gate, up);
    gemm2_kernel<<<dim3(HDIM / TN, TILE_MAX), blk>>>(down, ew);

    combine_kernel<<<(NTOK * (HDIM / 4) + 255) / 256, 256>>>(out);
}

// round 5
// speedup vs baseline: 2.3981x; 2.3981x over previous
#include <cuda_runtime.h>
#include <cuda_bf16.h>
#include <math.h>
#include <stdint.h>

// ---------------- problem constants ----------------
#define HDIM 1024
#define IDIM 4096
#define NEXP 8
#define NTOK 4096          // B*S
#define NSLOT 8192         // NTOK*TOPK
#define TM 128             // CTA M tile
#define TN 64              // CTA N tile
#define KC 32              // K elems per chunk
#define NCH1 (HDIM / KC)   // 32
#define NCH2 (IDIM / KC)   // 128
#define PAD_MAX 9216
#define TILE_MAX 72
#define STRD 40            // smem row stride in elems (32 + 8 pad) -> 80B rows

// ---------------- device scratch (static, no allocs) ----------------
__device__ int   g_perm[PAD_MAX];
__device__ int   g_tile_expert[TILE_MAX];
__device__ int   g_tile_row0[TILE_MAX];
// act stored pre-split as bf16 hi/lo, row-major [PAD_MAX][IDIM]
__device__ uint4 g_act_hi[(size_t)PAD_MAX * IDIM / 8];
__device__ uint4 g_act_lo[(size_t)PAD_MAX * IDIM / 8];
__device__ float g_y[(size_t)NSLOT * HDIM];

// ---------------- helpers ----------------
__device__ __forceinline__ uint32_t smem_to_u32(const void* p) {
    uint32_t a;
    asm("{ .reg .u64 t; cvta.to.shared.u64 t, %1; cvt.u32.u64 %0, t; }" : "=r"(a) : "l"(p));
    return a;
}

__device__ __forceinline__ void ldsm4(uint32_t* r, uint32_t addr) {
    asm volatile("ldmatrix.sync.aligned.m8n8.x4.shared.b16 {%0,%1,%2,%3}, [%4];"
                 : "=r"(r[0]), "=r"(r[1]), "=r"(r[2]), "=r"(r[3]) : "r"(addr));
}

__device__ __forceinline__ void mma16816(float* c, const uint32_t* a, uint32_t b0, uint32_t b1) {
    asm volatile(
        "mma.sync.aligned.m16n8k16.row.col.f32.bf16.bf16.f32 "
        "{%0,%1,%2,%3}, {%4,%5,%6,%7}, {%8,%9}, {%0,%1,%2,%3};"
        : "+f"(c[0]), "+f"(c[1]), "+f"(c[2]), "+f"(c[3])
        : "r"(a[0]), "r"(a[1]), "r"(a[2]), "r"(a[3]), "r"(b0), "r"(b1));
}

// ldmatrix x4 address for a 16(rows)x16(k) block at (row, k) in a [.][STRD] bf16 tile.
// lane 0-7: rows 0-7 @k, 8-15: rows 8-15 @k, 16-23: rows 0-7 @k+8, 24-31: rows 8-15 @k+8
__device__ __forceinline__ uint32_t lds_addr(uint32_t base, int row, int k, int lane) {
    int r = row + (lane & 15);
    int kk = k + ((lane >> 4) << 3);
    return base + (uint32_t)(r * (STRD * 2) + kk * 2);
}

__device__ __forceinline__ float silu_mul(float g, float u) {
    return g * u / (1.0f + expf(-g));
}

// split 8 fp32 into hi/lo bf16 (16B each)
__device__ __forceinline__ void split8(float4 v0, float4 v1, void* ph, void* pl) {
    float f[8] = {v0.x, v0.y, v0.z, v0.w, v1.x, v1.y, v1.z, v1.w};
    union { __nv_bfloat16 b[8]; uint4 u; } H, L;
#pragma unroll
    for (int j = 0; j < 8; j++) {
        __nv_bfloat16 h = __float2bfloat16(f[j]);
        H.b[j] = h;
        L.b[j] = __float2bfloat16(f[j] - __bfloat162float(h));
    }
    *(uint4*)ph = H.u;
    *(uint4*)pl = L.u;
}

// ---------------- routing (output-order invariant) ----------------
__global__ void route_kernel(const int* __restrict__ ei) {
    __shared__ int cnt[NEXP];
    __shared__ int cur[NEXP];
    int tid = threadIdx.x;
    if (tid < NEXP) cnt[tid] = 0;
    __syncthreads();
    for (int s = tid; s < NSLOT; s += blockDim.x) atomicAdd(&cnt[ei[s]], 1);
    __syncthreads();
    if (tid == 0) {
        int base = 0, tile = 0;
        for (int e = 0; e < NEXP; e++) {
            cur[e] = base;
            int nt = (cnt[e] + TM - 1) / TM;
            for (int j = 0; j < nt; j++) { g_tile_expert[tile] = e; g_tile_row0[tile] = base + j * TM; tile++; }
            base += nt * TM;
        }
        for (; tile < TILE_MAX; tile++) g_tile_expert[tile] = -1;
    }
    __syncthreads();
    for (int r = tid; r < PAD_MAX; r += blockDim.x) g_perm[r] = -1;
    __syncthreads();
    for (int s = tid; s < NSLOT; s += blockDim.x) {
        int e = ei[s];
        int pos = atomicAdd(&cur[e], 1);
        g_perm[pos] = s;
    }
}

// ---------------- GEMM1: act = silu(x.gateT) * (x.upT) ----------------
__global__ __launch_bounds__(256, 2)
void gemm1_mma(const float* __restrict__ x,
               const float* __restrict__ gate,
               const float* __restrict__ up) {
    int e = g_tile_expert[blockIdx.y];
    if (e < 0) return;
    int row0 = g_tile_row0[blockIdx.y];
    int i0 = blockIdx.x * TN;

    __shared__ __align__(16) __nv_bfloat16 sXH[TM * STRD], sXL[TM * STRD];
    __shared__ __align__(16) __nv_bfloat16 sGH[TN * STRD], sGL[TN * STRD];
    __shared__ __align__(16) __nv_bfloat16 sUH[TN * STRD], sUL[TN * STRD];
    __shared__ int toks[TM];

    int tid = threadIdx.x;
    int lane = tid & 31, wid = tid >> 5;
    int mw = (wid >> 2) * 64;      // warp M offset (0 or 64)
    int nw = (wid & 3) * 16;       // warp N offset

    if (tid < TM) {
        int p = g_perm[row0 + tid];
        toks[tid] = (p >= 0) ? (p >> 1) : -1;
    }
    __syncthreads();

    uint32_t bXH = smem_to_u32(sXH), bXL = smem_to_u32(sXL);
    uint32_t bGH = smem_to_u32(sGH), bGL = smem_to_u32(sGL);
    uint32_t bUH = smem_to_u32(sUH), bUL = smem_to_u32(sUL);
    const float* gbase = gate + (size_t)e * IDIM * HDIM;
    const float* ubase = up   + (size_t)e * IDIM * HDIM;

    float cg[4][2][4], cu[4][2][4];
#pragma unroll
    for (int mf = 0; mf < 4; mf++)
#pragma unroll
        for (int nf = 0; nf < 2; nf++)
#pragma unroll
            for (int q = 0; q < 4; q++) { cg[mf][nf][q] = 0.f; cu[mf][nf][q] = 0.f; }

    for (int ch = 0; ch < NCH1; ch++) {
        int h0 = ch * KC;
        // stage x (gathered rows): 512 tasks of 8 elems
#pragma unroll
        for (int l = 0; l < 2; l++) {
            int s = tid + l * 256;
            int row = s >> 2, k0 = (s & 3) << 3;
            int tok = toks[row];
            float4 v0 = make_float4(0.f, 0.f, 0.f, 0.f), v1 = v0;
            if (tok >= 0) {
                const float4* p = (const float4*)(x + (size_t)tok * HDIM + h0 + k0);
                v0 = p[0]; v1 = p[1];
            }
            int off = row * STRD + k0;
            split8(v0, v1, sXH + off, sXL + off);
        }
        // stage gate + up: 256 tasks
        {
            int row = tid >> 2, k0 = (tid & 3) << 3;
            int off = row * STRD + k0;
            const float4* pg = (const float4*)(gbase + (size_t)(i0 + row) * HDIM + h0 + k0);
            split8(pg[0], pg[1], sGH + off, sGL + off);
            const float4* pu = (const float4*)(ubase + (size_t)(i0 + row) * HDIM + h0 + k0);
            split8(pu[0], pu[1], sUH + off, sUL + off);
        }
        __syncthreads();

#pragma unroll
        for (int ks = 0; ks < 2; ks++) {
            int kb = ks * 16;
            uint32_t bgh[4], bgl[4], buh[4], bul[4];
            ldsm4(bgh, lds_addr(bGH, nw, kb, lane));
            ldsm4(bgl, lds_addr(bGL, nw, kb, lane));
            ldsm4(buh, lds_addr(bUH, nw, kb, lane));
            ldsm4(bul, lds_addr(bUL, nw, kb, lane));
#pragma unroll
            for (int mf = 0; mf < 4; mf++) {
                uint32_t ah[4], al[4];
                ldsm4(ah, lds_addr(bXH, mw + mf * 16, kb, lane));
                ldsm4(al, lds_addr(bXL, mw + mf * 16, kb, lane));
#pragma unroll
                for (int nf = 0; nf < 2; nf++) {
                    mma16816(cg[mf][nf], ah, bgh[nf], bgh[nf + 2]);
                    mma16816(cg[mf][nf], ah, bgl[nf], bgl[nf + 2]);
                    mma16816(cg[mf][nf], al, bgh[nf], bgh[nf + 2]);
                    mma16816(cu[mf][nf], ah, buh[nf], buh[nf + 2]);
                    mma16816(cu[mf][nf], ah, bul[nf], bul[nf + 2]);
                    mma16816(cu[mf][nf], al, buh[nf], buh[nf + 2]);
                }
            }
        }
        __syncthreads();
    }

    // epilogue: silu*mul, split, store hi/lo bf16 act
    __nv_bfloat16* AH = (__nv_bfloat16*)g_act_hi;
    __nv_bfloat16* AL = (__nv_bfloat16*)g_act_lo;
#pragma unroll
    for (int mf = 0; mf < 4; mf++) {
#pragma unroll
        for (int nf = 0; nf < 2; nf++) {
            int mg = row0 + mw + mf * 16 + (lane >> 2);
            int ng = i0 + nw + nf * 8 + ((lane & 3) << 1);
#pragma unroll
            for (int h = 0; h < 2; h++) {   // h=0: c0,c1 ; h=1: c2,c3 (row +8)
                float a0 = silu_mul(cg[mf][nf][h * 2],     cu[mf][nf][h * 2]);
                float a1 = silu_mul(cg[mf][nf][h * 2 + 1], cu[mf][nf][h * 2 + 1]);
                __nv_bfloat16 h0 = __float2bfloat16(a0), h1 = __float2bfloat16(a1);
                __nv_bfloat16 l0 = __float2bfloat16(a0 - __bfloat162float(h0));
                __nv_bfloat16 l1 = __float2bfloat16(a1 - __bfloat162float(h1));
                size_t idx = (size_t)(mg + h * 8) * IDIM + ng;
                *(__nv_bfloat162*)(AH + idx) = __halves2bfloat162(h0, h1);
                *(__nv_bfloat162*)(AL + idx) = __halves2bfloat162(l0, l1);
            }
        }
    }
}

// ---------------- GEMM2: y = ew * (act . downT) ----------------
__global__ __launch_bounds__(256, 2)
void gemm2_mma(const float* __restrict__ down,
               const float* __restrict__ ew) {
    int e = g_tile_expert[blockIdx.y];
    if (e < 0) return;
    int row0 = g_tile_row0[blockIdx.y];
    int hb = blockIdx.x * TN;

    __shared__ __align__(16) __nv_bfloat16 sAH[TM * STRD], sAL[TM * STRD];
    __shared__ __align__(16) __nv_bfloat16 sWH[TN * STRD], sWL[TN * STRD];
    __shared__ int   slots[TM];
    __shared__ float swt[TM];

    int tid = threadIdx.x;
    int lane = tid & 31, wid = tid >> 5;
    int mw = (wid >> 2) * 64;
    int nw = (wid & 3) * 16;

    if (tid < TM) {
        int p = g_perm[row0 + tid];
        slots[tid] = p;
        swt[tid] = (p >= 0) ? ew[p] : 0.f;
    }
    __syncthreads();

    uint32_t bAH = smem_to_u32(sAH), bAL = smem_to_u32(sAL);
    uint32_t bWH = smem_to_u32(sWH), bWL = smem_to_u32(sWL);
    const float* dbase = down + (size_t)e * HDIM * IDIM;
    const __nv_bfloat16* ahp = (const __nv_bfloat16*)g_act_hi;
    const __nv_bfloat16* alp = (const __nv_bfloat16*)g_act_lo;

    float acc[4][2][4];
#pragma unroll
    for (int mf = 0; mf < 4; mf++)
#pragma unroll
        for (int nf = 0; nf < 2; nf++)
#pragma unroll
            for (int q = 0; q < 4; q++) acc[mf][nf][q] = 0.f;

    for (int ch = 0; ch < NCH2; ch++) {
        int kc0 = ch * KC;
        // stage act (pure 16B copies, already split bf16)
#pragma unroll
        for (int l = 0; l < 2; l++) {
            int s = tid + l * 256;
            int row = s >> 2, k0 = (s & 3) << 3;
            size_t gx = (size_t)(row0 + row) * IDIM + kc0 + k0;
            int off = row * STRD + k0;
            *(uint4*)(sAH + off) = *(const uint4*)(ahp + gx);
            *(uint4*)(sAL + off) = *(const uint4*)(alp + gx);
        }
        // stage down (fp32 -> split)
        {
            int row = tid >> 2, k0 = (tid & 3) << 3;
            int off = row * STRD + k0;
            const float4* p = (const float4*)(dbase + (size_t)(hb + row) * IDIM + kc0 + k0);
            split8(p[0], p[1], sWH + off, sWL + off);
        }
        __syncthreads();

#pragma unroll
        for (int ks = 0; ks < 2; ks++) {
            int kb = ks * 16;
            uint32_t bwh[4], bwl[4];
            ldsm4(bwh, lds_addr(bWH, nw, kb, lane));
            ldsm4(bwl, lds_addr(bWL, nw, kb, lane));
#pragma unroll
            for (int mf = 0; mf < 4; mf++) {
                uint32_t ah[4], al[4];
                ldsm4(ah, lds_addr(bAH, mw + mf * 16, kb, lane));
                ldsm4(al, lds_addr(bAL, mw + mf * 16, kb, lane));
#pragma unroll
                for (int nf = 0; nf < 2; nf++) {
                    mma16816(acc[mf][nf], ah, bwh[nf], bwh[nf + 2]);
                    mma16816(acc[mf][nf], ah, bwl[nf], bwl[nf + 2]);
                    mma16816(acc[mf][nf], al, bwh[nf], bwh[nf + 2]);
                }
            }
        }
        __syncthreads();
    }

    // epilogue: scale by routing weight, scatter to per-slot y
#pragma unroll
    for (int mf = 0; mf < 4; mf++) {
#pragma unroll
        for (int nf = 0; nf < 2; nf++) {
            int ml = mw + mf * 16 + (lane >> 2);
            int ng = hb + nw + nf * 8 + ((lane & 3) << 1);
#pragma unroll
            for (int h = 0; h < 2; h++) {
                int m = ml + h * 8;
                int p = slots[m];
                if (p >= 0) {
                    float w = swt[m];
                    float2 o;
                    o.x = acc[mf][nf][h * 2] * w;
                    o.y = acc[mf][nf][h * 2 + 1] * w;
                    *(float2*)(g_y + (size_t)p * HDIM + ng) = o;
                }
            }
        }
    }
}

// ---------------- combine ----------------
__global__ void combine_kernel(float* __restrict__ out) {
    const int HQ = HDIM / 4;
    int i = blockIdx.x * blockDim.x + threadIdx.x;
    if (i >= NTOK * HQ) return;
    int t = i / HQ, hq = i - t * HQ;
    const float4* y4 = (const float4*)g_y;
    float4 a = y4[(size_t)(2 * t) * HQ + hq];
    float4 b = y4[(size_t)(2 * t + 1) * HQ + hq];
    float4 o;
    o.x = a.x + b.x; o.y = a.y + b.y; o.z = a.z + b.z; o.w = a.w + b.w;
    ((float4*)out)[(size_t)t * HQ + hq] = o;
}

extern "C" void kernel_launch(void* const* d_in, const int* in_sizes, int n_in,
                              void* d_out, int out_size) {
    const float* x    = (const float*)d_in[0];
    const int*   ei   = (const int*)d_in[1];
    const float* ew   = (const float*)d_in[2];
    const float* gate = (const float*)d_in[3];
    const float* up   = (const float*)d_in[4];
    const float* down = (const float*)d_in[5];
    float* out = (float*)d_out;

    route_kernel<<<1, 256>>>(ei);
    gemm1_mma<<<dim3(IDIM / TN, TILE_MAX), 256>>>(x, gate, up);
    gemm2_mma<<<dim3(HDIM / TN, TILE_MAX), 256>>>(down, ew);
    combine_kernel<<<(NTOK * (HDIM / 4) + 255) / 256, 256>>>(out);
}